// round 11
// baseline (speedup 1.0000x reference)
#include <cuda_runtime.h>
#include <cuda_bf16.h>
#include <cstdint>

// Problem constants
#define B_  2
#define S_  4096
#define HID_ 2560
#define H_  8
#define KV_ 4
#define D_  256
#define SW_ 1024
#define EPS_ 1e-6f
#define SCALE_ 0.0625f   // D^-0.5

#define NQKV_ 4096            // (H + 2*KV) * D
#define K3A_  7680            // 3 * HID
#define K3B_  6144            // 3 * (H*D)

// ---------------------------------------------------------------------------
// Scratch (device globals: allocation-free rule)
// ---------------------------------------------------------------------------
__device__ float g_q[(size_t)B_ * H_  * S_ * D_];     // [b,h,s,d]
__device__ float g_k[(size_t)B_ * KV_ * S_ * D_];
__device__ float g_v[(size_t)B_ * KV_ * S_ * D_];
__device__ float g_attn[(size_t)B_ * S_ * H_ * D_];   // [b,s,h*d]
__device__ __nv_bfloat16 g_a1[(size_t)B_ * S_ * K3A_];     // hidden expanded (hi,lo,hi)
__device__ __nv_bfloat16 g_wqkv[(size_t)NQKV_ * K3A_];     // [n, 3K] (hi,hi,lo)
__device__ __nv_bfloat16 g_a2[(size_t)B_ * S_ * K3B_];     // attn expanded
__device__ __nv_bfloat16 g_wo[(size_t)HID_ * K3B_];        // Wo^T expanded

// ---------------------------------------------------------------------------
// PTX helpers (base sm_103-safe)
// ---------------------------------------------------------------------------
__device__ __forceinline__ uint32_t smem_u32(const void* p) {
    uint32_t a;
    asm("{ .reg .u64 t; cvta.to.shared.u64 t, %1; cvt.u32.u64 %0, t; }" : "=r"(a) : "l"(p));
    return a;
}
__device__ __forceinline__ void cp_async16(uint32_t dst, const void* src) {
    asm volatile("cp.async.cg.shared.global [%0], [%1], 16;\n" :: "r"(dst), "l"(src));
}
#define CP_COMMIT() asm volatile("cp.async.commit_group;\n" ::: "memory")
#define CP_WAIT(n)  asm volatile("cp.async.wait_group %0;\n" :: "n"(n) : "memory")

__device__ __forceinline__ void ldmatrix_x4(uint32_t& r0, uint32_t& r1,
                                            uint32_t& r2, uint32_t& r3, uint32_t addr) {
    asm volatile("ldmatrix.sync.aligned.m8n8.x4.shared.b16 {%0,%1,%2,%3}, [%4];"
                 : "=r"(r0), "=r"(r1), "=r"(r2), "=r"(r3) : "r"(addr));
}
__device__ __forceinline__ void mma_bf16(float* d, const uint32_t* a, const uint32_t* b) {
    asm volatile(
        "mma.sync.aligned.m16n8k16.row.col.f32.bf16.bf16.f32 "
        "{%0,%1,%2,%3}, {%4,%5,%6,%7}, {%8,%9}, {%0,%1,%2,%3};"
        : "+f"(d[0]), "+f"(d[1]), "+f"(d[2]), "+f"(d[3])
        : "r"(a[0]), "r"(a[1]), "r"(a[2]), "r"(a[3]), "r"(b[0]), "r"(b[1]));
}

// Packed fp32 (Blackwell base ISA, verified working in R5)
#define FMA2(acc, a, b) \
    asm("fma.rn.f32x2 %0, %1, %2, %0;" : "+l"(acc) : "l"(a), "l"(b))
#define MUL2(acc, m) \
    asm("mul.rn.f32x2 %0, %0, %1;" : "+l"(acc) : "l"(m))
__device__ __forceinline__ unsigned long long pack2(float x, float y) {
    unsigned long long r;
    asm("mov.b64 %0, {%1, %2};" : "=l"(r) : "r"(__float_as_uint(x)), "r"(__float_as_uint(y)));
    return r;
}
__device__ __forceinline__ float lo2(unsigned long long v) { return __uint_as_float((uint32_t)v); }
__device__ __forceinline__ float hi2(unsigned long long v) { return __uint_as_float((uint32_t)(v >> 32)); }

// ---------------------------------------------------------------------------
// Expansion kernels: fp32 -> bf16 (hi, lo, hi) along 3K
// ---------------------------------------------------------------------------
__global__ void __launch_bounds__(256) expand_a_kernel(
    const float* __restrict__ A, __nv_bfloat16* __restrict__ out,
    int K, long long total4)
{
    long long i4 = (long long)blockIdx.x * 256 + threadIdx.x;
    if (i4 >= total4) return;
    long long base = i4 * 4;
    long long m = base / K;
    int k = (int)(base - m * K);
    float4 v = *(const float4*)(A + base);
    __nv_bfloat16* o = out + m * (long long)(3 * K) + k;
    float vs[4] = {v.x, v.y, v.z, v.w};
#pragma unroll
    for (int j = 0; j < 4; j++) {
        __nv_bfloat16 h = __float2bfloat16(vs[j]);
        __nv_bfloat16 l = __float2bfloat16(vs[j] - __bfloat162float(h));
        o[j] = h;
        o[K + j] = l;
        o[2 * K + j] = h;
    }
}

// W [K,N] row-major -> out [N, 3K] with (hi, hi, lo) at (k, K+k, 2K+k)
__global__ void expand_wt_kernel(
    const float* __restrict__ W, __nv_bfloat16* __restrict__ out, int K, int N)
{
    __shared__ float t[32][33];
    int n0 = blockIdx.x * 32, k0 = blockIdx.y * 32;
    int tx = threadIdx.x, ty = threadIdx.y;
#pragma unroll
    for (int j = 0; j < 32; j += 8)
        t[ty + j][tx] = W[(size_t)(k0 + ty + j) * N + n0 + tx];
    __syncthreads();
#pragma unroll
    for (int j = 0; j < 32; j += 8) {
        int n = n0 + ty + j;
        float v = t[tx][ty + j];
        __nv_bfloat16 h = __float2bfloat16(v);
        __nv_bfloat16 l = __float2bfloat16(v - __bfloat162float(h));
        __nv_bfloat16* o = out + (size_t)n * (3 * K) + k0 + tx;
        o[0] = h; o[K] = h; o[2 * K] = l;
    }
}

// ---------------------------------------------------------------------------
// bf16 mma.sync GEMM (exact R4 version — known good)
// ---------------------------------------------------------------------------
#define STG 3
#define STAGE_BYTES 32768
#define GEMM_SMEM (STG * STAGE_BYTES + 256)

__global__ void __launch_bounds__(256, 2) gemm_mma_kernel(
    const __nv_bfloat16* __restrict__ Ag, const __nv_bfloat16* __restrict__ Bg,
    float* __restrict__ o0, float* __restrict__ o1, float* __restrict__ o2,
    int K3, int NC, int Nout, int mode)
{
    extern __shared__ char dsm[];
    uint32_t smbase = (smem_u32(dsm) + 127) & ~127u;

    const int tid = threadIdx.x;
    const int wid = tid >> 5;
    const int lan = tid & 31;
    const int gRow0 = blockIdx.y * 128;
    const int gCol0 = blockIdx.x * 128;

    const int lrow = tid >> 3;
    const int lu   = tid & 7;
    const uint32_t swc = (uint32_t)((lu ^ (lrow & 7)) << 4);
    const char* arow = (const char*)(Ag + (size_t)(gRow0 + lrow) * K3 + lu * 8);
    const char* brow = (const char*)(Bg + (size_t)(gCol0 + lrow) * K3 + lu * 8);
    const size_t rstep = (size_t)32 * K3 * 2;

    const int wm = wid & 3;
    const int wn = wid >> 2;
    const int mbase = wm * 32;
    const int nbase = wn * 64;
    const int q8 = lan >> 3;
    const int r8 = lan & 7;

    int rowA[2];
#pragma unroll
    for (int mt = 0; mt < 2; mt++) rowA[mt] = mbase + mt * 16 + (q8 & 1) * 8 + r8;
    const int uqA = q8 >> 1;
    int rowB[4];
#pragma unroll
    for (int p = 0; p < 4; p++) rowB[p] = nbase + p * 16 + (q8 >> 1) * 8 + r8;
    const int uqB = q8 & 1;

    float acc[2][8][4];
#pragma unroll
    for (int mt = 0; mt < 2; mt++)
#pragma unroll
        for (int nt = 0; nt < 8; nt++)
#pragma unroll
            for (int e = 0; e < 4; e++) acc[mt][nt][e] = 0.f;

#pragma unroll
    for (int s = 0; s < STG - 1; s++) {
        uint32_t sA = smbase + s * STAGE_BYTES;
        uint32_t sB = sA + 16384;
        const char* ap = arow + (size_t)s * 128;
        const char* bp = brow + (size_t)s * 128;
#pragma unroll
        for (int i = 0; i < 4; i++) {
            uint32_t off = (uint32_t)((lrow + 32 * i) * 128) + swc;
            cp_async16(sA + off, ap + i * rstep);
            cp_async16(sB + off, bp + i * rstep);
        }
        CP_COMMIT();
    }

    for (int c = 0; c < NC; c++) {
        CP_WAIT(STG - 2);
        __syncthreads();

        {
            int cn = c + STG - 1;
            if (cn < NC) {
                uint32_t sA = smbase + (cn % STG) * STAGE_BYTES;
                uint32_t sB = sA + 16384;
                const char* ap = arow + (size_t)cn * 128;
                const char* bp = brow + (size_t)cn * 128;
#pragma unroll
                for (int i = 0; i < 4; i++) {
                    uint32_t off = (uint32_t)((lrow + 32 * i) * 128) + swc;
                    cp_async16(sA + off, ap + i * rstep);
                    cp_async16(sB + off, bp + i * rstep);
                }
            }
            CP_COMMIT();
        }

        uint32_t sA = smbase + (c % STG) * STAGE_BYTES;
        uint32_t sB = sA + 16384;

#pragma unroll
        for (int ks = 0; ks < 4; ks++) {
            uint32_t afr[2][4];
#pragma unroll
            for (int mt = 0; mt < 2; mt++) {
                uint32_t addr = sA + rowA[mt] * 128 + (((ks * 2 + uqA) ^ r8) << 4);
                ldmatrix_x4(afr[mt][0], afr[mt][1], afr[mt][2], afr[mt][3], addr);
            }
            uint32_t bfr[8][2];
#pragma unroll
            for (int p = 0; p < 4; p++) {
                uint32_t addr = sB + rowB[p] * 128 + (((ks * 2 + uqB) ^ r8) << 4);
                uint32_t r0, r1, r2, r3;
                ldmatrix_x4(r0, r1, r2, r3, addr);
                bfr[2 * p][0] = r0; bfr[2 * p][1] = r1;
                bfr[2 * p + 1][0] = r2; bfr[2 * p + 1][1] = r3;
            }
#pragma unroll
            for (int mt = 0; mt < 2; mt++)
#pragma unroll
                for (int nt = 0; nt < 8; nt++)
                    mma_bf16(acc[mt][nt], afr[mt], bfr[nt]);
        }
    }

    const int g4 = lan >> 2;
    const int t4 = lan & 3;

    if (mode == 1) {
#pragma unroll
        for (int mt = 0; mt < 2; mt++) {
#pragma unroll
            for (int rh = 0; rh < 2; rh++) {
                int gr = gRow0 + mbase + mt * 16 + rh * 8 + g4;
                float* rowp = o0 + (size_t)gr * Nout + gCol0 + nbase + t4 * 2;
#pragma unroll
                for (int nt = 0; nt < 8; nt++) {
                    float2 o;
                    o.x = acc[mt][nt][rh * 2 + 0];
                    o.y = acc[mt][nt][rh * 2 + 1];
                    *(float2*)(rowp + nt * 8) = o;
                }
            }
        }
    } else {
        int b = gRow0 >> 12;
        int srow0 = gRow0 & 4095;
        float* base;
        int head;
        if (gCol0 < 2048)      { head = gCol0 >> 8;          base = o0 + ((size_t)(b * H_  + head)) * S_ * D_; }
        else if (gCol0 < 3072) { head = (gCol0 - 2048) >> 8; base = o1 + ((size_t)(b * KV_ + head)) * S_ * D_; }
        else                   { head = (gCol0 - 3072) >> 8; base = o2 + ((size_t)(b * KV_ + head)) * S_ * D_; }
        int colAdd = (gCol0 & 255) + nbase + t4 * 2;
#pragma unroll
        for (int mt = 0; mt < 2; mt++) {
#pragma unroll
            for (int rh = 0; rh < 2; rh++) {
                int sr = srow0 + mbase + mt * 16 + rh * 8 + g4;
                float* rowp = base + (size_t)sr * D_ + colAdd;
#pragma unroll
                for (int nt = 0; nt < 8; nt++) {
                    float2 o;
                    o.x = acc[mt][nt][rh * 2 + 0];
                    o.y = acc[mt][nt][rh * 2 + 1];
                    *(float2*)(rowp + nt * 8) = o;
                }
            }
        }
    }
}

// ---------------------------------------------------------------------------
// RMSNorm + RoPE (in place). One block per (b, h, s) row of D=256.
// ---------------------------------------------------------------------------
__global__ void __launch_bounds__(256) norm_rope_kernel(
    float* __restrict__ x, const float* __restrict__ w,
    const float* __restrict__ cs, const float* __restrict__ sn, int NH)
{
    int s = blockIdx.x, h = blockIdx.y, b = blockIdx.z;
    int d = threadIdx.x;
    float* row = x + (((size_t)(b * NH + h)) * S_ + s) * D_;
    float val = row[d];

    __shared__ float red[8];
    __shared__ float xs[256];

    float sq = val * val;
#pragma unroll
    for (int off = 16; off; off >>= 1) sq += __shfl_xor_sync(0xffffffffu, sq, off);
    if ((d & 31) == 0) red[d >> 5] = sq;
    __syncthreads();
    if (d < 8) {
        float t = red[d];
#pragma unroll
        for (int off = 4; off; off >>= 1) t += __shfl_xor_sync(0xffu, t, off, 8);
        if (d == 0) red[0] = rsqrtf(t * (1.f / 256.f) + EPS_);
    }
    __syncthreads();
    float rinv = red[0];
    float xn = val * rinv * (1.f + w[d]);
    xs[d] = xn;
    __syncthreads();
    float rot = (d < 128) ? -xs[d + 128] : xs[d - 128];
    size_t ci = ((size_t)b * S_ + s) * D_ + d;
    row[d] = xn * cs[ci] + rot * sn[ci];
}

// ---------------------------------------------------------------------------
// Flash attention, sliding window 1024.
// Packed f32x2 math (one pack per scalar, float4 P loads), R4 epilogue.
// One CTA per (64 q rows, head, batch). 256 threads, 1 CTA/SM (smem-bound).
// ---------------------------------------------------------------------------
#define ATT_SMEM_FLOATS (3 * 64 * 256 + 64 * 68 + 3 * 64)
#define ATT_SMEM_BYTES  (ATT_SMEM_FLOATS * 4)

__global__ void __launch_bounds__(256) attn_kernel(
    const float* __restrict__ q, const float* __restrict__ k,
    const float* __restrict__ v, float* __restrict__ out)
{
    extern __shared__ float sm[];
    float* Qs   = sm;
    float* Ks   = Qs + 64 * 256;
    float* Vs   = Ks + 64 * 256;
    float* Ps   = Vs + 64 * 256;
    float* mrow = Ps + 64 * 68;
    float* lrow = mrow + 64;
    float* crow = lrow + 64;

    const int qb = blockIdx.x, h = blockIdx.y, b = blockIdx.z;
    const int q0 = qb * 64;
    const int tid = threadIdx.x;
    const int tx = tid & 15, ty = tid >> 4;
    const int kvh = h >> 1;

    const float* qbase = q + (((size_t)(b * H_ + h)) * S_ + q0) * D_;
    const float* kbase = k + (((size_t)(b * KV_ + kvh)) * S_) * (size_t)D_;
    const float* vbase = v + (((size_t)(b * KV_ + kvh)) * S_) * (size_t)D_;

    for (int vv = tid; vv < 64 * 64; vv += 256) {
        int i = vv >> 6, dq = vv & 63;
        *(float4*)&Qs[i * 256 + dq * 4] = *(const float4*)&qbase[(size_t)i * 256 + dq * 4];
    }
    if (tid < 64) { mrow[tid] = -1e30f; lrow[tid] = 0.f; }

    // O accumulators: 4 rows x 8 packed pairs (16 cols), ascending d order
    unsigned long long O2[4][8];
#pragma unroll
    for (int r = 0; r < 4; r++)
#pragma unroll
        for (int c = 0; c < 8; c++) O2[r][c] = 0ull;

    const int iO = (tid >> 4) * 4;
    const int dO = (tid & 15) * 16;
    const int i0 = ty * 4, j0 = tx * 4;

    const int kb0 = (qb >= 16) ? (qb - 16) : 0;
    for (int kb = kb0; kb <= qb; kb++) {
        __syncthreads();
        const float* kp = kbase + (size_t)kb * 64 * D_;
        const float* vp = vbase + (size_t)kb * 64 * D_;
        for (int vv = tid; vv < 64 * 64; vv += 256) {
            int i = vv >> 6, dq = vv & 63;
            *(float4*)&Ks[i * 256 + dq * 4] = *(const float4*)&kp[(size_t)i * 256 + dq * 4];
            *(float4*)&Vs[i * 256 + dq * 4] = *(const float4*)&vp[(size_t)i * 256 + dq * 4];
        }
        __syncthreads();

        // S = Q K^T, packed over d pairs
        unsigned long long acc2[4][4];
#pragma unroll
        for (int r = 0; r < 4; r++)
#pragma unroll
            for (int c = 0; c < 4; c++) acc2[r][c] = 0ull;

#pragma unroll 4
        for (int d = 0; d < 256; d += 4) {
            ulonglong2 a2[4], b2[4];
#pragma unroll
            for (int r = 0; r < 4; r++) a2[r] = *(ulonglong2*)&Qs[(i0 + r) * 256 + d];
#pragma unroll
            for (int c = 0; c < 4; c++) b2[c] = *(ulonglong2*)&Ks[(j0 + c) * 256 + d];
#pragma unroll
            for (int r = 0; r < 4; r++)
#pragma unroll
                for (int c = 0; c < 4; c++) {
                    FMA2(acc2[r][c], a2[r].x, b2[c].x);
                    FMA2(acc2[r][c], a2[r].y, b2[c].y);
                }
        }

        // scale + mask + online softmax
#pragma unroll
        for (int r = 0; r < 4; r++) {
            int ig = q0 + i0 + r;
            float sv[4];
            float mx = -1e30f;
#pragma unroll
            for (int c = 0; c < 4; c++) {
                int jg = kb * 64 + j0 + c;
                float s = (lo2(acc2[r][c]) + hi2(acc2[r][c])) * SCALE_;
                if (jg > ig || (ig - jg) > SW_) s = -1e30f;
                sv[c] = s;
                mx = fmaxf(mx, s);
            }
#pragma unroll
            for (int off = 8; off >= 1; off >>= 1)
                mx = fmaxf(mx, __shfl_xor_sync(0xffffffffu, mx, off, 16));
            float m_old = mrow[i0 + r];
            float m_new = fmaxf(m_old, mx);
            float ls = 0.f;
#pragma unroll
            for (int c = 0; c < 4; c++) {
                float p = __expf(sv[c] - m_new);
                ls += p;
                Ps[(i0 + r) * 68 + j0 + c] = p;
            }
#pragma unroll
            for (int off = 8; off >= 1; off >>= 1)
                ls += __shfl_xor_sync(0xffffffffu, ls, off, 16);
            if (tx == 0) {
                crow[i0 + r] = __expf(m_old - m_new);
                mrow[i0 + r] = m_new;
                lrow[i0 + r] = lrow[i0 + r] * __expf(m_old - m_new) + ls;
            }
        }
        __syncthreads();

        // O = O*corr + P @ V, packed pairs, P via float4
#pragma unroll
        for (int r = 0; r < 4; r++) {
            float cc = crow[iO + r];
            unsigned long long cc2 = pack2(cc, cc);
#pragma unroll
            for (int c = 0; c < 8; c++) MUL2(O2[r][c], cc2);
        }

        for (int j4 = 0; j4 < 64; j4 += 4) {
            float4 pr[4];
#pragma unroll
            for (int r = 0; r < 4; r++) pr[r] = *(float4*)&Ps[(iO + r) * 68 + j4];
#pragma unroll
            for (int jj = 0; jj < 4; jj++) {
                const float* vrow = &Vs[(j4 + jj) * 256 + dO];
                ulonglong2 v0 = *(ulonglong2*)(vrow + 0);   // d pairs 0,1
                ulonglong2 v1 = *(ulonglong2*)(vrow + 4);   // d pairs 2,3
                ulonglong2 v2 = *(ulonglong2*)(vrow + 8);   // d pairs 4,5
                ulonglong2 v3 = *(ulonglong2*)(vrow + 12);  // d pairs 6,7
#pragma unroll
                for (int r = 0; r < 4; r++) {
                    float p = (jj == 0) ? pr[r].x : (jj == 1) ? pr[r].y
                             : (jj == 2) ? pr[r].z : pr[r].w;
                    unsigned long long pp = pack2(p, p);
                    FMA2(O2[r][0], pp, v0.x);
                    FMA2(O2[r][1], pp, v0.y);
                    FMA2(O2[r][2], pp, v1.x);
                    FMA2(O2[r][3], pp, v1.y);
                    FMA2(O2[r][4], pp, v2.x);
                    FMA2(O2[r][5], pp, v2.y);
                    FMA2(O2[r][6], pp, v3.x);
                    FMA2(O2[r][7], pp, v3.y);
                }
            }
        }
    }

    // normalize + coalesced float4 store to g_attn [b, s, h*D + d]
#pragma unroll
    for (int r = 0; r < 4; r++) {
        float inv = 1.f / lrow[iO + r];
        size_t base = ((size_t)b * S_ + (q0 + iO + r)) * (size_t)(H_ * D_) + h * D_ + dO;
#pragma unroll
        for (int cg = 0; cg < 4; cg++) {
            float4 o;
            o.x = lo2(O2[r][cg * 2 + 0]) * inv;
            o.y = hi2(O2[r][cg * 2 + 0]) * inv;
            o.z = lo2(O2[r][cg * 2 + 1]) * inv;
            o.w = hi2(O2[r][cg * 2 + 1]) * inv;
            *(float4*)&out[base + cg * 4] = o;
        }
    }
}

// ---------------------------------------------------------------------------
// Launch
// ---------------------------------------------------------------------------
extern "C" void kernel_launch(void* const* d_in, const int* in_sizes, int n_in,
                              void* d_out, int out_size)
{
    const float* hidden = (const float*)d_in[0];
    const float* cosT   = (const float*)d_in[1];
    const float* sinT   = (const float*)d_in[2];
    const float* Wq     = (const float*)d_in[3];
    const float* Wk     = (const float*)d_in[4];
    const float* Wv     = (const float*)d_in[5];
    const float* Wo     = (const float*)d_in[6];
    const float* qnw    = (const float*)d_in[7];
    const float* knw    = (const float*)d_in[8];
    float* outp = (float*)d_out;

    float *pq, *pk, *pv, *pattn;
    __nv_bfloat16 *pa1, *pwqkv, *pa2, *pwo;
    cudaGetSymbolAddress((void**)&pq, g_q);
    cudaGetSymbolAddress((void**)&pk, g_k);
    cudaGetSymbolAddress((void**)&pv, g_v);
    cudaGetSymbolAddress((void**)&pattn, g_attn);
    cudaGetSymbolAddress((void**)&pa1, g_a1);
    cudaGetSymbolAddress((void**)&pwqkv, g_wqkv);
    cudaGetSymbolAddress((void**)&pa2, g_a2);
    cudaGetSymbolAddress((void**)&pwo, g_wo);

    const int M = B_ * S_;  // 8192

    // ---- expand inputs/weights to bf16 hi/lo triplets ----
    {
        long long tot4 = (long long)M * HID_ / 4;
        expand_a_kernel<<<(unsigned)((tot4 + 255) / 256), 256>>>(hidden, pa1, HID_, tot4);
    }
    {
        dim3 blk(32, 8);
        expand_wt_kernel<<<dim3(2048 / 32, HID_ / 32), blk>>>(Wq, pwqkv, HID_, 2048);
        expand_wt_kernel<<<dim3(1024 / 32, HID_ / 32), blk>>>(Wk, pwqkv + (size_t)2048 * K3A_, HID_, 1024);
        expand_wt_kernel<<<dim3(1024 / 32, HID_ / 32), blk>>>(Wv, pwqkv + (size_t)3072 * K3A_, HID_, 1024);
        expand_wt_kernel<<<dim3(HID_ / 32, (H_ * D_) / 32), blk>>>(Wo, pwo, H_ * D_, HID_);
    }

    // ---- fused QKV projection (mma.sync) ----
    cudaFuncSetAttribute(gemm_mma_kernel, cudaFuncAttributeMaxDynamicSharedMemorySize, GEMM_SMEM);
    gemm_mma_kernel<<<dim3(NQKV_ / 128, M / 128), 256, GEMM_SMEM>>>(
        pa1, pwqkv, pq, pk, pv, K3A_, K3A_ / 64, 0, 0);

    // ---- RMSNorm + RoPE ----
    norm_rope_kernel<<<dim3(S_, H_, B_), 256>>>(pq, qnw, cosT, sinT, H_);
    norm_rope_kernel<<<dim3(S_, KV_, B_), 256>>>(pk, knw, cosT, sinT, KV_);

    // ---- sliding-window attention ----
    cudaFuncSetAttribute(attn_kernel, cudaFuncAttributeMaxDynamicSharedMemorySize, ATT_SMEM_BYTES);
    attn_kernel<<<dim3(S_ / 64, H_, B_), 256, ATT_SMEM_BYTES>>>(pq, pk, pv, pattn);

    // ---- output projection ----
    {
        long long tot4 = (long long)M * (H_ * D_) / 4;
        expand_a_kernel<<<(unsigned)((tot4 + 255) / 256), 256>>>(pattn, pa2, H_ * D_, tot4);
    }
    gemm_mma_kernel<<<dim3(HID_ / 128, M / 128), 256, GEMM_SMEM>>>(
        pa2, pwo, outp, nullptr, nullptr, K3B_, K3B_ / 64, HID_, 1);
}

// round 12
// speedup vs baseline: 1.0009x; 1.0009x over previous
#include <cuda_runtime.h>
#include <cuda_bf16.h>
#include <cstdint>

// Problem constants
#define B_  2
#define S_  4096
#define HID_ 2560
#define H_  8
#define KV_ 4
#define D_  256
#define SW_ 1024
#define EPS_ 1e-6f
#define SCALE_ 0.0625f   // D^-0.5

#define NQKV_ 4096            // (H + 2*KV) * D
#define K3A_  7680            // 3 * HID
#define K3B_  6144            // 3 * (H*D)

// ---------------------------------------------------------------------------
// Scratch (device globals: allocation-free rule)
// ---------------------------------------------------------------------------
__device__ float g_q[(size_t)B_ * H_  * S_ * D_];     // [b,h,s,d]
__device__ float g_k[(size_t)B_ * KV_ * S_ * D_];
__device__ float g_v[(size_t)B_ * KV_ * S_ * D_];
__device__ float g_attn[(size_t)B_ * S_ * H_ * D_];   // [b,s,h*d]
__device__ __nv_bfloat16 g_a1[(size_t)B_ * S_ * K3A_];     // hidden expanded (hi,lo,hi)
__device__ __nv_bfloat16 g_wqkv[(size_t)NQKV_ * K3A_];     // [n, 3K] (hi,hi,lo)
__device__ __nv_bfloat16 g_a2[(size_t)B_ * S_ * K3B_];     // attn expanded
__device__ __nv_bfloat16 g_wo[(size_t)HID_ * K3B_];        // Wo^T expanded

// ---------------------------------------------------------------------------
// PTX helpers (base sm_103-safe)
// ---------------------------------------------------------------------------
__device__ __forceinline__ uint32_t smem_u32(const void* p) {
    uint32_t a;
    asm("{ .reg .u64 t; cvta.to.shared.u64 t, %1; cvt.u32.u64 %0, t; }" : "=r"(a) : "l"(p));
    return a;
}
__device__ __forceinline__ void cp_async16(uint32_t dst, const void* src) {
    asm volatile("cp.async.cg.shared.global [%0], [%1], 16;\n" :: "r"(dst), "l"(src));
}
#define CP_COMMIT() asm volatile("cp.async.commit_group;\n" ::: "memory")
#define CP_WAIT(n)  asm volatile("cp.async.wait_group %0;\n" :: "n"(n) : "memory")

__device__ __forceinline__ void ldmatrix_x4(uint32_t& r0, uint32_t& r1,
                                            uint32_t& r2, uint32_t& r3, uint32_t addr) {
    asm volatile("ldmatrix.sync.aligned.m8n8.x4.shared.b16 {%0,%1,%2,%3}, [%4];"
                 : "=r"(r0), "=r"(r1), "=r"(r2), "=r"(r3) : "r"(addr));
}
__device__ __forceinline__ void mma_bf16(float* d, const uint32_t* a, const uint32_t* b) {
    asm volatile(
        "mma.sync.aligned.m16n8k16.row.col.f32.bf16.bf16.f32 "
        "{%0,%1,%2,%3}, {%4,%5,%6,%7}, {%8,%9}, {%0,%1,%2,%3};"
        : "+f"(d[0]), "+f"(d[1]), "+f"(d[2]), "+f"(d[3])
        : "r"(a[0]), "r"(a[1]), "r"(a[2]), "r"(a[3]), "r"(b[0]), "r"(b[1]));
}

// Packed fp32 (Blackwell base ISA, verified working in R5)
#define FMA2(acc, a, b) \
    asm("fma.rn.f32x2 %0, %1, %2, %0;" : "+l"(acc) : "l"(a), "l"(b))
#define MUL2(acc, m) \
    asm("mul.rn.f32x2 %0, %0, %1;" : "+l"(acc) : "l"(m))
__device__ __forceinline__ unsigned long long pack2(float x, float y) {
    unsigned long long r;
    asm("mov.b64 %0, {%1, %2};" : "=l"(r) : "r"(__float_as_uint(x)), "r"(__float_as_uint(y)));
    return r;
}
__device__ __forceinline__ float lo2(unsigned long long v) { return __uint_as_float((uint32_t)v); }
__device__ __forceinline__ float hi2(unsigned long long v) { return __uint_as_float((uint32_t)(v >> 32)); }

// ---------------------------------------------------------------------------
// Expansion kernels: fp32 -> bf16 (hi, lo, hi) along 3K
// ---------------------------------------------------------------------------
__global__ void __launch_bounds__(256) expand_a_kernel(
    const float* __restrict__ A, __nv_bfloat16* __restrict__ out,
    int K, long long total4)
{
    long long i4 = (long long)blockIdx.x * 256 + threadIdx.x;
    if (i4 >= total4) return;
    long long base = i4 * 4;
    long long m = base / K;
    int k = (int)(base - m * K);
    float4 v = *(const float4*)(A + base);
    __nv_bfloat16* o = out + m * (long long)(3 * K) + k;
    float vs[4] = {v.x, v.y, v.z, v.w};
#pragma unroll
    for (int j = 0; j < 4; j++) {
        __nv_bfloat16 h = __float2bfloat16(vs[j]);
        __nv_bfloat16 l = __float2bfloat16(vs[j] - __bfloat162float(h));
        o[j] = h;
        o[K + j] = l;
        o[2 * K + j] = h;
    }
}

// W [K,N] row-major -> out [N, 3K] with (hi, hi, lo) at (k, K+k, 2K+k)
__global__ void expand_wt_kernel(
    const float* __restrict__ W, __nv_bfloat16* __restrict__ out, int K, int N)
{
    __shared__ float t[32][33];
    int n0 = blockIdx.x * 32, k0 = blockIdx.y * 32;
    int tx = threadIdx.x, ty = threadIdx.y;
#pragma unroll
    for (int j = 0; j < 32; j += 8)
        t[ty + j][tx] = W[(size_t)(k0 + ty + j) * N + n0 + tx];
    __syncthreads();
#pragma unroll
    for (int j = 0; j < 32; j += 8) {
        int n = n0 + ty + j;
        float v = t[tx][ty + j];
        __nv_bfloat16 h = __float2bfloat16(v);
        __nv_bfloat16 l = __float2bfloat16(v - __bfloat162float(h));
        __nv_bfloat16* o = out + (size_t)n * (3 * K) + k0 + tx;
        o[0] = h; o[K] = h; o[2 * K] = l;
    }
}

// ---------------------------------------------------------------------------
// bf16 mma.sync GEMM (exact R4 version — known good)
// ---------------------------------------------------------------------------
#define STG 3
#define STAGE_BYTES 32768
#define GEMM_SMEM (STG * STAGE_BYTES + 256)

__global__ void __launch_bounds__(256, 2) gemm_mma_kernel(
    const __nv_bfloat16* __restrict__ Ag, const __nv_bfloat16* __restrict__ Bg,
    float* __restrict__ o0, float* __restrict__ o1, float* __restrict__ o2,
    int K3, int NC, int Nout, int mode)
{
    extern __shared__ char dsm[];
    uint32_t smbase = (smem_u32(dsm) + 127) & ~127u;

    const int tid = threadIdx.x;
    const int wid = tid >> 5;
    const int lan = tid & 31;
    const int gRow0 = blockIdx.y * 128;
    const int gCol0 = blockIdx.x * 128;

    const int lrow = tid >> 3;
    const int lu   = tid & 7;
    const uint32_t swc = (uint32_t)((lu ^ (lrow & 7)) << 4);
    const char* arow = (const char*)(Ag + (size_t)(gRow0 + lrow) * K3 + lu * 8);
    const char* brow = (const char*)(Bg + (size_t)(gCol0 + lrow) * K3 + lu * 8);
    const size_t rstep = (size_t)32 * K3 * 2;

    const int wm = wid & 3;
    const int wn = wid >> 2;
    const int mbase = wm * 32;
    const int nbase = wn * 64;
    const int q8 = lan >> 3;
    const int r8 = lan & 7;

    int rowA[2];
#pragma unroll
    for (int mt = 0; mt < 2; mt++) rowA[mt] = mbase + mt * 16 + (q8 & 1) * 8 + r8;
    const int uqA = q8 >> 1;
    int rowB[4];
#pragma unroll
    for (int p = 0; p < 4; p++) rowB[p] = nbase + p * 16 + (q8 >> 1) * 8 + r8;
    const int uqB = q8 & 1;

    float acc[2][8][4];
#pragma unroll
    for (int mt = 0; mt < 2; mt++)
#pragma unroll
        for (int nt = 0; nt < 8; nt++)
#pragma unroll
            for (int e = 0; e < 4; e++) acc[mt][nt][e] = 0.f;

#pragma unroll
    for (int s = 0; s < STG - 1; s++) {
        uint32_t sA = smbase + s * STAGE_BYTES;
        uint32_t sB = sA + 16384;
        const char* ap = arow + (size_t)s * 128;
        const char* bp = brow + (size_t)s * 128;
#pragma unroll
        for (int i = 0; i < 4; i++) {
            uint32_t off = (uint32_t)((lrow + 32 * i) * 128) + swc;
            cp_async16(sA + off, ap + i * rstep);
            cp_async16(sB + off, bp + i * rstep);
        }
        CP_COMMIT();
    }

    for (int c = 0; c < NC; c++) {
        CP_WAIT(STG - 2);
        __syncthreads();

        {
            int cn = c + STG - 1;
            if (cn < NC) {
                uint32_t sA = smbase + (cn % STG) * STAGE_BYTES;
                uint32_t sB = sA + 16384;
                const char* ap = arow + (size_t)cn * 128;
                const char* bp = brow + (size_t)cn * 128;
#pragma unroll
                for (int i = 0; i < 4; i++) {
                    uint32_t off = (uint32_t)((lrow + 32 * i) * 128) + swc;
                    cp_async16(sA + off, ap + i * rstep);
                    cp_async16(sB + off, bp + i * rstep);
                }
            }
            CP_COMMIT();
        }

        uint32_t sA = smbase + (c % STG) * STAGE_BYTES;
        uint32_t sB = sA + 16384;

#pragma unroll
        for (int ks = 0; ks < 4; ks++) {
            uint32_t afr[2][4];
#pragma unroll
            for (int mt = 0; mt < 2; mt++) {
                uint32_t addr = sA + rowA[mt] * 128 + (((ks * 2 + uqA) ^ r8) << 4);
                ldmatrix_x4(afr[mt][0], afr[mt][1], afr[mt][2], afr[mt][3], addr);
            }
            uint32_t bfr[8][2];
#pragma unroll
            for (int p = 0; p < 4; p++) {
                uint32_t addr = sB + rowB[p] * 128 + (((ks * 2 + uqB) ^ r8) << 4);
                uint32_t r0, r1, r2, r3;
                ldmatrix_x4(r0, r1, r2, r3, addr);
                bfr[2 * p][0] = r0; bfr[2 * p][1] = r1;
                bfr[2 * p + 1][0] = r2; bfr[2 * p + 1][1] = r3;
            }
#pragma unroll
            for (int mt = 0; mt < 2; mt++)
#pragma unroll
                for (int nt = 0; nt < 8; nt++)
                    mma_bf16(acc[mt][nt], afr[mt], bfr[nt]);
        }
    }

    const int g4 = lan >> 2;
    const int t4 = lan & 3;

    if (mode == 1) {
#pragma unroll
        for (int mt = 0; mt < 2; mt++) {
#pragma unroll
            for (int rh = 0; rh < 2; rh++) {
                int gr = gRow0 + mbase + mt * 16 + rh * 8 + g4;
                float* rowp = o0 + (size_t)gr * Nout + gCol0 + nbase + t4 * 2;
#pragma unroll
                for (int nt = 0; nt < 8; nt++) {
                    float2 o;
                    o.x = acc[mt][nt][rh * 2 + 0];
                    o.y = acc[mt][nt][rh * 2 + 1];
                    *(float2*)(rowp + nt * 8) = o;
                }
            }
        }
    } else {
        int b = gRow0 >> 12;
        int srow0 = gRow0 & 4095;
        float* base;
        int head;
        if (gCol0 < 2048)      { head = gCol0 >> 8;          base = o0 + ((size_t)(b * H_  + head)) * S_ * D_; }
        else if (gCol0 < 3072) { head = (gCol0 - 2048) >> 8; base = o1 + ((size_t)(b * KV_ + head)) * S_ * D_; }
        else                   { head = (gCol0 - 3072) >> 8; base = o2 + ((size_t)(b * KV_ + head)) * S_ * D_; }
        int colAdd = (gCol0 & 255) + nbase + t4 * 2;
#pragma unroll
        for (int mt = 0; mt < 2; mt++) {
#pragma unroll
            for (int rh = 0; rh < 2; rh++) {
                int sr = srow0 + mbase + mt * 16 + rh * 8 + g4;
                float* rowp = base + (size_t)sr * D_ + colAdd;
#pragma unroll
                for (int nt = 0; nt < 8; nt++) {
                    float2 o;
                    o.x = acc[mt][nt][rh * 2 + 0];
                    o.y = acc[mt][nt][rh * 2 + 1];
                    *(float2*)(rowp + nt * 8) = o;
                }
            }
        }
    }
}

// ---------------------------------------------------------------------------
// RMSNorm + RoPE (in place). One block per (b, h, s) row of D=256.
// ---------------------------------------------------------------------------
__global__ void __launch_bounds__(256) norm_rope_kernel(
    float* __restrict__ x, const float* __restrict__ w,
    const float* __restrict__ cs, const float* __restrict__ sn, int NH)
{
    int s = blockIdx.x, h = blockIdx.y, b = blockIdx.z;
    int d = threadIdx.x;
    float* row = x + (((size_t)(b * NH + h)) * S_ + s) * D_;
    float val = row[d];

    __shared__ float red[8];
    __shared__ float xs[256];

    float sq = val * val;
#pragma unroll
    for (int off = 16; off; off >>= 1) sq += __shfl_xor_sync(0xffffffffu, sq, off);
    if ((d & 31) == 0) red[d >> 5] = sq;
    __syncthreads();
    if (d < 8) {
        float t = red[d];
#pragma unroll
        for (int off = 4; off; off >>= 1) t += __shfl_xor_sync(0xffu, t, off, 8);
        if (d == 0) red[0] = rsqrtf(t * (1.f / 256.f) + EPS_);
    }
    __syncthreads();
    float rinv = red[0];
    float xn = val * rinv * (1.f + w[d]);
    xs[d] = xn;
    __syncthreads();
    float rot = (d < 128) ? -xs[d + 128] : xs[d - 128];
    size_t ci = ((size_t)b * S_ + s) * D_ + d;
    row[d] = xn * cs[ci] + rot * sn[ci];
}

// ---------------------------------------------------------------------------
// Flash attention, sliding window 1024.
// Packed f32x2 math (one pack per scalar, float4 P loads), R4 epilogue.
// One CTA per (64 q rows, head, batch). 256 threads, 1 CTA/SM (smem-bound).
// ---------------------------------------------------------------------------
#define ATT_SMEM_FLOATS (3 * 64 * 256 + 64 * 68 + 3 * 64)
#define ATT_SMEM_BYTES  (ATT_SMEM_FLOATS * 4)

__global__ void __launch_bounds__(256) attn_kernel(
    const float* __restrict__ q, const float* __restrict__ k,
    const float* __restrict__ v, float* __restrict__ out)
{
    extern __shared__ float sm[];
    float* Qs   = sm;
    float* Ks   = Qs + 64 * 256;
    float* Vs   = Ks + 64 * 256;
    float* Ps   = Vs + 64 * 256;
    float* mrow = Ps + 64 * 68;
    float* lrow = mrow + 64;
    float* crow = lrow + 64;

    const int qb = blockIdx.x, h = blockIdx.y, b = blockIdx.z;
    const int q0 = qb * 64;
    const int tid = threadIdx.x;
    const int tx = tid & 15, ty = tid >> 4;
    const int kvh = h >> 1;

    const float* qbase = q + (((size_t)(b * H_ + h)) * S_ + q0) * D_;
    const float* kbase = k + (((size_t)(b * KV_ + kvh)) * S_) * (size_t)D_;
    const float* vbase = v + (((size_t)(b * KV_ + kvh)) * S_) * (size_t)D_;

    for (int vv = tid; vv < 64 * 64; vv += 256) {
        int i = vv >> 6, dq = vv & 63;
        *(float4*)&Qs[i * 256 + dq * 4] = *(const float4*)&qbase[(size_t)i * 256 + dq * 4];
    }
    if (tid < 64) { mrow[tid] = -1e30f; lrow[tid] = 0.f; }

    // O accumulators: 4 rows x 8 packed pairs (16 cols), ascending d order
    unsigned long long O2[4][8];
#pragma unroll
    for (int r = 0; r < 4; r++)
#pragma unroll
        for (int c = 0; c < 8; c++) O2[r][c] = 0ull;

    const int iO = (tid >> 4) * 4;
    const int dO = (tid & 15) * 16;
    const int i0 = ty * 4, j0 = tx * 4;

    const int kb0 = (qb >= 16) ? (qb - 16) : 0;
    for (int kb = kb0; kb <= qb; kb++) {
        __syncthreads();
        const float* kp = kbase + (size_t)kb * 64 * D_;
        const float* vp = vbase + (size_t)kb * 64 * D_;
        for (int vv = tid; vv < 64 * 64; vv += 256) {
            int i = vv >> 6, dq = vv & 63;
            *(float4*)&Ks[i * 256 + dq * 4] = *(const float4*)&kp[(size_t)i * 256 + dq * 4];
            *(float4*)&Vs[i * 256 + dq * 4] = *(const float4*)&vp[(size_t)i * 256 + dq * 4];
        }
        __syncthreads();

        // S = Q K^T, packed over d pairs
        unsigned long long acc2[4][4];
#pragma unroll
        for (int r = 0; r < 4; r++)
#pragma unroll
            for (int c = 0; c < 4; c++) acc2[r][c] = 0ull;

#pragma unroll 4
        for (int d = 0; d < 256; d += 4) {
            ulonglong2 a2[4], b2[4];
#pragma unroll
            for (int r = 0; r < 4; r++) a2[r] = *(ulonglong2*)&Qs[(i0 + r) * 256 + d];
#pragma unroll
            for (int c = 0; c < 4; c++) b2[c] = *(ulonglong2*)&Ks[(j0 + c) * 256 + d];
#pragma unroll
            for (int r = 0; r < 4; r++)
#pragma unroll
                for (int c = 0; c < 4; c++) {
                    FMA2(acc2[r][c], a2[r].x, b2[c].x);
                    FMA2(acc2[r][c], a2[r].y, b2[c].y);
                }
        }

        // scale + mask + online softmax
#pragma unroll
        for (int r = 0; r < 4; r++) {
            int ig = q0 + i0 + r;
            float sv[4];
            float mx = -1e30f;
#pragma unroll
            for (int c = 0; c < 4; c++) {
                int jg = kb * 64 + j0 + c;
                float s = (lo2(acc2[r][c]) + hi2(acc2[r][c])) * SCALE_;
                if (jg > ig || (ig - jg) > SW_) s = -1e30f;
                sv[c] = s;
                mx = fmaxf(mx, s);
            }
#pragma unroll
            for (int off = 8; off >= 1; off >>= 1)
                mx = fmaxf(mx, __shfl_xor_sync(0xffffffffu, mx, off, 16));
            float m_old = mrow[i0 + r];
            float m_new = fmaxf(m_old, mx);
            float ls = 0.f;
#pragma unroll
            for (int c = 0; c < 4; c++) {
                float p = __expf(sv[c] - m_new);
                ls += p;
                Ps[(i0 + r) * 68 + j0 + c] = p;
            }
#pragma unroll
            for (int off = 8; off >= 1; off >>= 1)
                ls += __shfl_xor_sync(0xffffffffu, ls, off, 16);
            if (tx == 0) {
                crow[i0 + r] = __expf(m_old - m_new);
                mrow[i0 + r] = m_new;
                lrow[i0 + r] = lrow[i0 + r] * __expf(m_old - m_new) + ls;
            }
        }
        __syncthreads();

        // O = O*corr + P @ V, packed pairs, P via float4
#pragma unroll
        for (int r = 0; r < 4; r++) {
            float cc = crow[iO + r];
            unsigned long long cc2 = pack2(cc, cc);
#pragma unroll
            for (int c = 0; c < 8; c++) MUL2(O2[r][c], cc2);
        }

        for (int j4 = 0; j4 < 64; j4 += 4) {
            float4 pr[4];
#pragma unroll
            for (int r = 0; r < 4; r++) pr[r] = *(float4*)&Ps[(iO + r) * 68 + j4];
#pragma unroll
            for (int jj = 0; jj < 4; jj++) {
                const float* vrow = &Vs[(j4 + jj) * 256 + dO];
                ulonglong2 v0 = *(ulonglong2*)(vrow + 0);   // d pairs 0,1
                ulonglong2 v1 = *(ulonglong2*)(vrow + 4);   // d pairs 2,3
                ulonglong2 v2 = *(ulonglong2*)(vrow + 8);   // d pairs 4,5
                ulonglong2 v3 = *(ulonglong2*)(vrow + 12);  // d pairs 6,7
#pragma unroll
                for (int r = 0; r < 4; r++) {
                    float p = (jj == 0) ? pr[r].x : (jj == 1) ? pr[r].y
                             : (jj == 2) ? pr[r].z : pr[r].w;
                    unsigned long long pp = pack2(p, p);
                    FMA2(O2[r][0], pp, v0.x);
                    FMA2(O2[r][1], pp, v0.y);
                    FMA2(O2[r][2], pp, v1.x);
                    FMA2(O2[r][3], pp, v1.y);
                    FMA2(O2[r][4], pp, v2.x);
                    FMA2(O2[r][5], pp, v2.y);
                    FMA2(O2[r][6], pp, v3.x);
                    FMA2(O2[r][7], pp, v3.y);
                }
            }
        }
    }

    // normalize + coalesced float4 store to g_attn [b, s, h*D + d]
#pragma unroll
    for (int r = 0; r < 4; r++) {
        float inv = 1.f / lrow[iO + r];
        size_t base = ((size_t)b * S_ + (q0 + iO + r)) * (size_t)(H_ * D_) + h * D_ + dO;
#pragma unroll
        for (int cg = 0; cg < 4; cg++) {
            float4 o;
            o.x = lo2(O2[r][cg * 2 + 0]) * inv;
            o.y = hi2(O2[r][cg * 2 + 0]) * inv;
            o.z = lo2(O2[r][cg * 2 + 1]) * inv;
            o.w = hi2(O2[r][cg * 2 + 1]) * inv;
            *(float4*)&out[base + cg * 4] = o;
        }
    }
}

// ---------------------------------------------------------------------------
// Launch
// ---------------------------------------------------------------------------
extern "C" void kernel_launch(void* const* d_in, const int* in_sizes, int n_in,
                              void* d_out, int out_size)
{
    const float* hidden = (const float*)d_in[0];
    const float* cosT   = (const float*)d_in[1];
    const float* sinT   = (const float*)d_in[2];
    const float* Wq     = (const float*)d_in[3];
    const float* Wk     = (const float*)d_in[4];
    const float* Wv     = (const float*)d_in[5];
    const float* Wo     = (const float*)d_in[6];
    const float* qnw    = (const float*)d_in[7];
    const float* knw    = (const float*)d_in[8];
    float* outp = (float*)d_out;

    float *pq, *pk, *pv, *pattn;
    __nv_bfloat16 *pa1, *pwqkv, *pa2, *pwo;
    cudaGetSymbolAddress((void**)&pq, g_q);
    cudaGetSymbolAddress((void**)&pk, g_k);
    cudaGetSymbolAddress((void**)&pv, g_v);
    cudaGetSymbolAddress((void**)&pattn, g_attn);
    cudaGetSymbolAddress((void**)&pa1, g_a1);
    cudaGetSymbolAddress((void**)&pwqkv, g_wqkv);
    cudaGetSymbolAddress((void**)&pa2, g_a2);
    cudaGetSymbolAddress((void**)&pwo, g_wo);

    const int M = B_ * S_;  // 8192

    // ---- expand inputs/weights to bf16 hi/lo triplets ----
    {
        long long tot4 = (long long)M * HID_ / 4;
        expand_a_kernel<<<(unsigned)((tot4 + 255) / 256), 256>>>(hidden, pa1, HID_, tot4);
    }
    {
        dim3 blk(32, 8);
        expand_wt_kernel<<<dim3(2048 / 32, HID_ / 32), blk>>>(Wq, pwqkv, HID_, 2048);
        expand_wt_kernel<<<dim3(1024 / 32, HID_ / 32), blk>>>(Wk, pwqkv + (size_t)2048 * K3A_, HID_, 1024);
        expand_wt_kernel<<<dim3(1024 / 32, HID_ / 32), blk>>>(Wv, pwqkv + (size_t)3072 * K3A_, HID_, 1024);
        expand_wt_kernel<<<dim3(HID_ / 32, (H_ * D_) / 32), blk>>>(Wo, pwo, H_ * D_, HID_);
    }

    // ---- fused QKV projection (mma.sync) ----
    cudaFuncSetAttribute(gemm_mma_kernel, cudaFuncAttributeMaxDynamicSharedMemorySize, GEMM_SMEM);
    gemm_mma_kernel<<<dim3(NQKV_ / 128, M / 128), 256, GEMM_SMEM>>>(
        pa1, pwqkv, pq, pk, pv, K3A_, K3A_ / 64, 0, 0);

    // ---- RMSNorm + RoPE ----
    norm_rope_kernel<<<dim3(S_, H_, B_), 256>>>(pq, qnw, cosT, sinT, H_);
    norm_rope_kernel<<<dim3(S_, KV_, B_), 256>>>(pk, knw, cosT, sinT, KV_);

    // ---- sliding-window attention ----
    cudaFuncSetAttribute(attn_kernel, cudaFuncAttributeMaxDynamicSharedMemorySize, ATT_SMEM_BYTES);
    attn_kernel<<<dim3(S_ / 64, H_, B_), 256, ATT_SMEM_BYTES>>>(pq, pk, pv, pattn);

    // ---- output projection ----
    {
        long long tot4 = (long long)M * (H_ * D_) / 4;
        expand_a_kernel<<<(unsigned)((tot4 + 255) / 256), 256>>>(pattn, pa2, H_ * D_, tot4);
    }
    gemm_mma_kernel<<<dim3(HID_ / 128, M / 128), 256, GEMM_SMEM>>>(
        pa2, pwo, outp, nullptr, nullptr, K3B_, K3B_ / 64, HID_, 1);
}